// round 14
// baseline (speedup 1.0000x reference)
#include <cuda_runtime.h>
#include <cuda_fp16.h>
#include <math.h>
#include <stdint.h>

// Shapes (fixed by the problem)
#define NB 6
#define HEADS 12
#define DIM 768
#define EHD 32
#define HE 384
#define NKV 768          // fused K|V projection width
#define LQ 64
#define SK 512
#define BATCH 64
#define HID 3072
#define MQ (BATCH*LQ)   // 4096
#define MKV (BATCH*SK)  // 32768

// ------------------------- scratch (device globals; no allocs) -------------
__device__ float g_x  [MQ  * DIM];
__device__ float g_t  [MQ  * DIM];

// fp16 activations
__device__ __half g_xh [MQ * DIM];
__device__ __half g_eh [MKV * DIM];
__device__ __half g_Qh [MQ * HE];
__device__ __half g_KVh[MKV * NKV];
__device__ __half g_Oh [MQ * HE];
__device__ __half g_Hh [MQ * HID];

// fp16 weights, repacked to [N][K] per block
__device__ __half g_wq [NB*HE*DIM];
__device__ __half g_wkv[NB*NKV*DIM];
__device__ __half g_wo [NB*DIM*HE];
__device__ __half g_w1 [NB*HID*DIM];
__device__ __half g_w2 [NB*DIM*HID];

// ------------------------- helpers ----------------------------------------
__device__ __forceinline__ float gelu_exact(float v)
{
    return 0.5f * v * (1.0f + erff(v * 0.70710678118654752f));
}
__device__ __forceinline__ uint32_t smaddr(const void* p)
{
    return (uint32_t)__cvta_generic_to_shared(p);
}
__device__ __forceinline__ void cp16(uint32_t dst, const void* src)
{
    asm volatile("cp.async.cg.shared.global [%0], [%1], 16;" :: "r"(dst), "l"(src));
}
__device__ __forceinline__ void ldsm4(uint32_t a[4], uint32_t addr)
{
    asm volatile("ldmatrix.sync.aligned.m8n8.x4.shared.b16 {%0,%1,%2,%3}, [%4];"
                 : "=r"(a[0]), "=r"(a[1]), "=r"(a[2]), "=r"(a[3]) : "r"(addr));
}
__device__ __forceinline__ void mma16816(float c[4], const uint32_t a[4],
                                         uint32_t b0, uint32_t b1)
{
    asm volatile(
        "mma.sync.aligned.m16n8k16.row.col.f32.f16.f16.f32 "
        "{%0,%1,%2,%3}, {%4,%5,%6,%7}, {%8,%9}, {%0,%1,%2,%3};"
        : "+f"(c[0]), "+f"(c[1]), "+f"(c[2]), "+f"(c[3])
        : "r"(a[0]), "r"(a[1]), "r"(a[2]), "r"(a[3]), "r"(b0), "r"(b1));
}
__device__ __forceinline__ uint32_t pack_h2(float x, float y)
{
    __half2 h = __floats2half2_rn(x, y);
    return *(uint32_t*)&h;
}

// ------------------------- repack kernels ----------------------------------
__global__ void repack_qkv(const float* __restrict__ w, __half* __restrict__ o)
{
    int idx = blockIdx.x * blockDim.x + threadIdx.x;
    const int total = NB * HE * DIM;
    if (idx >= total) return;
    int i = idx / (HE * DIM);
    int r = idx % (HE * DIM);
    int n = r / DIM, d = r % DIM;
    int h = n >> 5, e = n & 31;
    o[idx] = __float2half(w[(((long)i * HEADS + h) * DIM + d) * EHD + e]);
}
__global__ void repack_kv(const float* __restrict__ wk, const float* __restrict__ wv,
                          __half* __restrict__ o)
{
    int idx = blockIdx.x * blockDim.x + threadIdx.x;
    const int total = NB * NKV * DIM;
    if (idx >= total) return;
    int i = idx / (NKV * DIM);
    int r = idx % (NKV * DIM);
    int n = r / DIM, d = r % DIM;
    const float* src = (n < HE) ? wk : wv;
    int nn = (n < HE) ? n : n - HE;
    int h = nn >> 5, e = nn & 31;
    o[idx] = __float2half(src[(((long)i * HEADS + h) * DIM + d) * EHD + e]);
}
__global__ void repack_wo(const float* __restrict__ w, __half* __restrict__ o)
{
    int idx = blockIdx.x * blockDim.x + threadIdx.x;
    const int total = NB * DIM * HE;
    if (idx >= total) return;
    int i = idx / (DIM * HE);
    int r = idx % (DIM * HE);
    int n = r / HE, k = r % HE;
    o[idx] = __float2half(w[((long)i * HE + k) * DIM + n]);
}
__global__ void repack_ffn(const float* __restrict__ w, __half* __restrict__ o,
                           int Kd, int Nd)
{
    int idx = blockIdx.x * blockDim.x + threadIdx.x;
    const int total = NB * Kd * Nd;
    if (idx >= total) return;
    int i = idx / (Nd * Kd);
    int r = idx % (Nd * Kd);
    int n = r / Kd, k = r % Kd;
    o[idx] = __float2half(w[((long)i * Kd + k) * Nd + n]);
}

__global__ void cvt4_kernel(const float* __restrict__ x,
                            __half* __restrict__ h, int n4)
{
    int i = blockIdx.x * blockDim.x + threadIdx.x;
    if (i >= n4) return;
    float4 v = ((const float4*)x)[i];
    __half2* H = (__half2*)(h + 4*(long)i);
    H[0] = __floats2half2_rn(v.x, v.y);
    H[1] = __floats2half2_rn(v.z, v.w);
}

__global__ void init_x_kernel(const float* __restrict__ pos, float* __restrict__ x,
                              __half* __restrict__ xh)
{
    int idx = blockIdx.x * blockDim.x + threadIdx.x;
    const int total = MQ * DIM;
    if (idx >= total) return;
    int rowq = (idx / DIM) % LQ;
    int d    = idx % DIM;
    float v = pos[rowq * DIM + d];
    x[idx] = v;
    xh[idx] = __float2half(v);
}

// ------------------------- pipelined tensor-core GEMM ----------------------
// C[M,N] = A[M,K] @ W[N,K]^T, all fp16 operands, fp32 accum.
// mode 0: fp32   mode 1: GELU->fp16   mode 2: +R fp32   mode 3: fp16
#define KS 32
#define LDSS 40
#define TILE_E (128 * LDSS)
#define STAGE_E (2 * TILE_E)          // A, B
#define GEMM_SMEM (2 * STAGE_E * 2)   // 2 stages, bytes (40960)

__global__ void __launch_bounds__(256, 2) mma_gemm(
    const __half* __restrict__ A, const __half* __restrict__ B,
    const float* __restrict__ R, float* __restrict__ C,
    __half* __restrict__ Ch,
    int M, int N, int K, int mode)
{
    extern __shared__ __half smem[];
    const uint32_t sbase = smaddr(smem);

    const int t    = threadIdx.x;
    const int lane = t & 31;
    const int warp = t >> 5;
    const int wm   = (warp & 1) * 64;
    const int wn   = (warp >> 1) * 32;
    const long bm  = (long)blockIdx.x * 128;
    const long bn  = (long)blockIdx.y * 128;

    const int lrow = lane & 15;
    const int lcol = (lane >> 4) * 8;

    float c[4][4][4];
#pragma unroll
    for (int a = 0; a < 4; ++a)
#pragma unroll
        for (int b = 0; b < 4; ++b)
#pragma unroll
            for (int d = 0; d < 4; ++d) c[a][b][d] = 0.f;

    const int T = K / KS;

    auto load_stage = [&](int buf, int k0) {
        uint32_t sb = sbase + (uint32_t)(buf * STAGE_E) * 2;
#pragma unroll
        for (int i = 0; i < 2; ++i) {
            int lin = t + i * 256;
            int row = lin >> 2;
            int ce  = (lin & 3) * 8;
            uint32_t off = (uint32_t)(row * LDSS + ce) * 2;
            cp16(sb + off,              A + (bm + row) * (long)K + k0 + ce);
            cp16(sb + TILE_E * 2 + off, B + (bn + row) * (long)K + k0 + ce);
        }
        asm volatile("cp.async.commit_group;");
    };

    load_stage(0, 0);

    for (int s = 0; s < T; ++s) {
        const int cur = s & 1;
        if (s + 1 < T) {
            load_stage(cur ^ 1, (s + 1) * KS);
            asm volatile("cp.async.wait_group 1;");
        } else {
            asm volatile("cp.async.wait_group 0;");
        }
        __syncthreads();

        const __half* sA = smem + cur * STAGE_E;
        const __half* sB = sA + TILE_E;

#pragma unroll
        for (int kk = 0; kk < KS; kk += 16) {
            uint32_t ah[4][4];
#pragma unroll
            for (int mt = 0; mt < 4; ++mt) {
                int r = (wm + mt * 16 + lrow) * LDSS + kk + lcol;
                ldsm4(ah[mt], smaddr(&sA[r]));
            }
#pragma unroll
            for (int ng = 0; ng < 2; ++ng) {
                uint32_t bh[4];
                int r = (wn + ng * 16 + lrow) * LDSS + kk + lcol;
                ldsm4(bh, smaddr(&sB[r]));
#pragma unroll
                for (int hf = 0; hf < 2; ++hf) {
                    int nt = ng * 2 + hf;
                    uint32_t b0 = bh[hf], b1 = bh[hf + 2];
#pragma unroll
                    for (int mt = 0; mt < 4; ++mt)
                        mma16816(c[mt][nt], ah[mt], b0, b1);
                }
            }
        }
        __syncthreads();
    }

    // ---- epilogue ----
#pragma unroll
    for (int mt = 0; mt < 4; ++mt) {
        long row0e = bm + wm + mt * 16 + (lane >> 2);
#pragma unroll
        for (int nt = 0; nt < 4; ++nt) {
            int col = (int)bn + wn + nt * 8 + (lane & 3) * 2;
#pragma unroll
            for (int hfr = 0; hfr < 2; ++hfr) {
                long row = row0e + hfr * 8;
                float vx = c[mt][nt][hfr * 2 + 0];
                float vy = c[mt][nt][hfr * 2 + 1];
                if (mode == 2) {
                    float2 r = *(const float2*)&R[row * N + col];
                    float2 v; v.x = vx + r.x; v.y = vy + r.y;
                    *(float2*)&C[row * N + col] = v;
                } else if (mode == 1) {
                    vx = gelu_exact(vx); vy = gelu_exact(vy);
                    *(__half2*)&Ch[row * N + col] = __floats2half2_rn(vx, vy);
                } else if (mode == 3) {
                    *(__half2*)&Ch[row * N + col] = __floats2half2_rn(vx, vy);
                } else {
                    float2 v; v.x = vx; v.y = vy;
                    *(float2*)&C[row * N + col] = v;
                }
            }
        }
    }
}

// ------------------------- LayerNorm (row per CTA), fused fp16 out ---------
__global__ void __launch_bounds__(256) ln_kernel(
    const float* __restrict__ in, const float* __restrict__ gg,
    const float* __restrict__ bb, float* __restrict__ out,
    __half* __restrict__ oh)
{
    const int row = blockIdx.x;
    const float* x = in + (long)row * DIM;
    const int t = threadIdx.x;

    float v0 = x[t], v1 = x[t + 256], v2 = x[t + 512];
    float s  = v0 + v1 + v2;
    float ss = v0 * v0 + v1 * v1 + v2 * v2;

    __shared__ float sh[16];
#pragma unroll
    for (int o = 16; o; o >>= 1) {
        s  += __shfl_xor_sync(0xffffffffu, s, o);
        ss += __shfl_xor_sync(0xffffffffu, ss, o);
    }
    int w = t >> 5, l = t & 31;
    if (l == 0) { sh[w] = s; sh[w + 8] = ss; }
    __syncthreads();
    s  = sh[0] + sh[1] + sh[2] + sh[3] + sh[4] + sh[5] + sh[6] + sh[7];
    ss = sh[8] + sh[9] + sh[10] + sh[11] + sh[12] + sh[13] + sh[14] + sh[15];

    const float mean = s * (1.0f / DIM);
    const float var  = ss * (1.0f / DIM) - mean * mean;
    const float inv  = rsqrtf(var + 1e-6f);

    float* o = out + (long)row * DIM;
    __half* ph = oh + (long)row * DIM;
#pragma unroll
    for (int j = 0; j < 3; ++j) {
        int idx = t + j * 256;
        float vv = (j == 0 ? v0 : (j == 1 ? v1 : v2));
        float r = (vv - mean) * inv * gg[idx] + bb[idx];
        o[idx] = r;
        ph[idx] = __float2half(r);
    }
}

// ------------------------- tensor-core attention ---------------------------
// one CTA per (b,h). Q[64x32], K[512x32] fp16; S fp32 smem; V^T [32x512] fp16.
#define ALD 40            // fp16 stride for Q/K rows (32+8)
#define VLD 520           // fp16 stride for V^T rows (512+8)
#define SPW 516           // fp32 stride for S rows
#define OFF_K  2560       // half offset of K
#define OFF_VT 23040      // half offset of V^T
#define OFF_P  79360      // BYTE offset of S/P (fp32)
#define ATTN_SMEM (OFF_P + 64 * SPW * 4)   // 211456 bytes

__global__ void __launch_bounds__(256) attn_kernel(
    const __half* __restrict__ Q, const __half* __restrict__ KV,
    __half* __restrict__ Oh)
{
    extern __shared__ char smc[];
    __half* sQ  = (__half*)smc;
    __half* sK  = (__half*)smc + OFF_K;
    __half* sVt = (__half*)smc + OFF_VT;
    float*  sP  = (float*)(smc + OFF_P);

    const int t = threadIdx.x;
    const int lane = t & 31;
    const int warp = t >> 5;
    const int b = blockIdx.x / HEADS;
    const int h = blockIdx.x % HEADS;
    const float scale = 0.03608439182435161f;  // 768^-0.5

    const __half* Qg = Q  + ((long)b * LQ) * HE  + h * EHD;
    const __half* Kg = KV + ((long)b * SK) * NKV + h * EHD;
    const __half* Vg = Kg + HE;

    {
        int row = t >> 2, ch = (t & 3) * 8;
        *(uint4*)&sQ[row * ALD + ch] = *(const uint4*)&Qg[(long)row * HE + ch];
    }
#pragma unroll
    for (int i = 0; i < 8; ++i) {
        int lin = t + i * 256;
        int row = lin >> 2, ch = (lin & 3) * 8;
        *(uint4*)&sK[row * ALD + ch] = *(const uint4*)&Kg[(long)row * NKV + ch];
    }
#pragma unroll
    for (int i = 0; i < 8; ++i) {
        int lin = t + i * 256;
        int tok = lin >> 2, e0 = (lin & 3) * 8;
        uint4 v = *(const uint4*)&Vg[(long)tok * NKV + e0];
        const __half* hv = (const __half*)&v;
#pragma unroll
        for (int j = 0; j < 8; ++j)
            sVt[(e0 + j) * VLD + tok] = hv[j];
    }
    __syncthreads();

    const int lrow = lane & 15;
    const int lcol = (lane >> 4) * 8;
    const int r  = lane >> 2;
    const int cc = (lane & 3) * 2;

    // ---- phase 1: S = Q @ K^T * scale ----
    {
        const int wm  = (warp & 3) * 16;
        const int wn0 = (warp >> 2) * 256;
        uint32_t aq[2][4];
#pragma unroll
        for (int k2 = 0; k2 < 2; ++k2)
            ldsm4(aq[k2], smaddr(&sQ[(wm + lrow) * ALD + k2 * 16 + lcol]));

#pragma unroll 4
        for (int ng = 0; ng < 16; ++ng) {
            float c0[4] = {0,0,0,0}, c1[4] = {0,0,0,0};
#pragma unroll
            for (int k2 = 0; k2 < 2; ++k2) {
                uint32_t bk[4];
                ldsm4(bk, smaddr(&sK[(wn0 + ng * 16 + lrow) * ALD + k2 * 16 + lcol]));
                mma16816(c0, aq[k2], bk[0], bk[2]);
                mma16816(c1, aq[k2], bk[1], bk[3]);
            }
            int col = wn0 + ng * 16;
            float2 v;
            v.x = c0[0] * scale; v.y = c0[1] * scale;
            *(float2*)&sP[(wm + r) * SPW + col + cc] = v;
            v.x = c0[2] * scale; v.y = c0[3] * scale;
            *(float2*)&sP[(wm + r + 8) * SPW + col + cc] = v;
            v.x = c1[0] * scale; v.y = c1[1] * scale;
            *(float2*)&sP[(wm + r) * SPW + col + 8 + cc] = v;
            v.x = c1[2] * scale; v.y = c1[3] * scale;
            *(float2*)&sP[(wm + r + 8) * SPW + col + 8 + cc] = v;
        }
    }
    __syncthreads();

    // ---- phase 2: softmax ----
    {
        const int q = t >> 2, part = t & 3;
        float* row = sP + q * SPW;
        const int s_lo = part * 128, s_hi = s_lo + 128;
        float mx = -1e30f;
        for (int s = s_lo; s < s_hi; ++s) mx = fmaxf(mx, row[s]);
        mx = fmaxf(mx, __shfl_xor_sync(0xffffffffu, mx, 1));
        mx = fmaxf(mx, __shfl_xor_sync(0xffffffffu, mx, 2));
        float sum = 0.f;
        for (int s = s_lo; s < s_hi; ++s) {
            float ev = __expf(row[s] - mx);
            row[s] = ev;
            sum += ev;
        }
        sum += __shfl_xor_sync(0xffffffffu, sum, 1);
        sum += __shfl_xor_sync(0xffffffffu, sum, 2);
        float inv = 1.0f / sum;
        for (int s = s_lo; s < s_hi; ++s) row[s] *= inv;
    }
    __syncthreads();

    // ---- phase 3: O = P @ V ----
    {
        const int wm = (warp & 3) * 16;
        const int wn = (warp >> 2) * 16;
        float o0[4] = {0,0,0,0}, o1[4] = {0,0,0,0};

#pragma unroll 4
        for (int kk = 0; kk < SK; kk += 16) {
            const float* p0 = &sP[(wm + r) * SPW + kk];
            const float* p1 = &sP[(wm + r + 8) * SPW + kk];
            float2 q00 = *(const float2*)&p0[cc];
            float2 q10 = *(const float2*)&p1[cc];
            float2 q01 = *(const float2*)&p0[cc + 8];
            float2 q11 = *(const float2*)&p1[cc + 8];
            uint32_t a[4];
            a[0] = pack_h2(q00.x, q00.y);
            a[1] = pack_h2(q10.x, q10.y);
            a[2] = pack_h2(q01.x, q01.y);
            a[3] = pack_h2(q11.x, q11.y);
            uint32_t bv[4];
            ldsm4(bv, smaddr(&sVt[(wn + lrow) * VLD + kk + lcol]));
            mma16816(o0, a, bv[0], bv[2]);
            mma16816(o1, a, bv[1], bv[3]);
        }

        long ob = ((long)b * LQ) * HE + h * EHD;
        *(__half2*)&Oh[ob + (long)(wm + r) * HE + wn + cc]
            = __floats2half2_rn(o0[0], o0[1]);
        *(__half2*)&Oh[ob + (long)(wm + r + 8) * HE + wn + cc]
            = __floats2half2_rn(o0[2], o0[3]);
        *(__half2*)&Oh[ob + (long)(wm + r) * HE + wn + 8 + cc]
            = __floats2half2_rn(o1[0], o1[1]);
        *(__half2*)&Oh[ob + (long)(wm + r + 8) * HE + wn + 8 + cc]
            = __floats2half2_rn(o1[2], o1[3]);
    }
}

// ------------------------- driver ------------------------------------------
extern "C" void kernel_launch(void* const* d_in, const int* in_sizes, int n_in,
                              void* d_out, int out_size)
{
    const float* enc  = (const float*)d_in[0];
    const float* pos  = (const float*)d_in[1];
    const float* wq   = (const float*)d_in[2];
    const float* wk   = (const float*)d_in[3];
    const float* wv   = (const float*)d_in[4];
    const float* wo   = (const float*)d_in[5];
    const float* ln1g = (const float*)d_in[6];
    const float* ln1b = (const float*)d_in[7];
    const float* ln2g = (const float*)d_in[8];
    const float* ln2b = (const float*)d_in[9];
    const float* w1   = (const float*)d_in[10];
    const float* w2   = (const float*)d_in[11];

    float *x, *tmp;
    cudaGetSymbolAddress((void**)&x,   g_x);
    cudaGetSymbolAddress((void**)&tmp, g_t);

    __half *xh,*eh,*Qh,*KVh,*Oh,*Hh;
    cudaGetSymbolAddress((void**)&xh,  g_xh);
    cudaGetSymbolAddress((void**)&eh,  g_eh);
    cudaGetSymbolAddress((void**)&Qh,  g_Qh);
    cudaGetSymbolAddress((void**)&KVh, g_KVh);
    cudaGetSymbolAddress((void**)&Oh,  g_Oh);
    cudaGetSymbolAddress((void**)&Hh,  g_Hh);

    __half *wqp,*wkvp,*wop,*w1p,*w2p;
    cudaGetSymbolAddress((void**)&wqp,  g_wq);
    cudaGetSymbolAddress((void**)&wkvp, g_wkv);
    cudaGetSymbolAddress((void**)&wop,  g_wo);
    cudaGetSymbolAddress((void**)&w1p,  g_w1);
    cudaGetSymbolAddress((void**)&w2p,  g_w2);

    cudaFuncSetAttribute(attn_kernel, cudaFuncAttributeMaxDynamicSharedMemorySize,
                         ATTN_SMEM);
    cudaFuncSetAttribute(mma_gemm, cudaFuncAttributeMaxDynamicSharedMemorySize,
                         GEMM_SMEM);

    {
        int n = NB * HE * DIM;
        repack_qkv<<<(n + 255) / 256, 256>>>(wq, wqp);
        repack_wo <<<(n + 255) / 256, 256>>>(wo, wop);
        int nkv = NB * NKV * DIM;
        repack_kv<<<(nkv + 255) / 256, 256>>>(wk, wv, wkvp);
        int nf = NB * DIM * HID;
        repack_ffn<<<(nf + 255) / 256, 256>>>(w1, w1p, DIM, HID);
        repack_ffn<<<(nf + 255) / 256, 256>>>(w2, w2p, HID, DIM);
    }
    init_x_kernel<<<(MQ * DIM + 255) / 256, 256>>>(pos, x, xh);
    cvt4_kernel<<<(MKV * DIM / 4 + 255) / 256, 256>>>(enc, eh, MKV * DIM / 4);

    dim3 gQ  (MQ  / 128, HE  / 128);  // 32 x 3
    dim3 gKV (MKV / 128, NKV / 128);  // 256 x 6
    dim3 gO  (MQ  / 128, DIM / 128);  // 32 x 6
    dim3 gF1 (MQ  / 128, HID / 128);  // 32 x 24
    dim3 gF2 (MQ  / 128, DIM / 128);  // 32 x 6

    for (int i = 0; i < NB; ++i) {
        const long woff   = (long)i * DIM * HE;
        const long wkvoff = (long)i * DIM * NKV;
        const long w1off  = (long)i * DIM * HID;
        const long w2off  = (long)i * HID * DIM;

        mma_gemm<<<gQ,  256, GEMM_SMEM>>>(xh, wqp + woff,
                                          nullptr, nullptr, Qh, MQ,  HE, DIM, 3);
        mma_gemm<<<gKV, 256, GEMM_SMEM>>>(eh, wkvp + wkvoff,
                                          nullptr, nullptr, KVh, MKV, NKV, DIM, 3);

        attn_kernel<<<BATCH * HEADS, 256, ATTN_SMEM>>>(Qh, KVh, Oh);

        mma_gemm<<<gO, 256, GEMM_SMEM>>>(Oh, wop + woff,
                                         x, tmp, nullptr, MQ, DIM, HE, 2);
        ln_kernel<<<MQ, 256>>>(tmp, ln1g + i * DIM, ln1b + i * DIM, x, xh);

        mma_gemm<<<gF1, 256, GEMM_SMEM>>>(xh, w1p + w1off,
                                          nullptr, nullptr, Hh, MQ, HID, DIM, 1);
        mma_gemm<<<gF2, 256, GEMM_SMEM>>>(Hh, w2p + w2off,
                                          x, tmp, nullptr, MQ, DIM, HID, 2);
        ln_kernel<<<MQ, 256>>>(tmp, ln2g + i * DIM, ln2b + i * DIM,
                               (i == NB - 1) ? (float*)d_out : x, xh);
    }
}

// round 15
// speedup vs baseline: 1.0048x; 1.0048x over previous
#include <cuda_runtime.h>
#include <cuda_fp16.h>
#include <math.h>
#include <stdint.h>

// Shapes (fixed by the problem)
#define NB 6
#define HEADS 12
#define DIM 768
#define EHD 32
#define HE 384
#define NKV 768          // fused K|V projection width
#define LQ 64
#define SK 512
#define BATCH 64
#define HID 3072
#define MQ (BATCH*LQ)   // 4096
#define MKV (BATCH*SK)  // 32768

// ------------------------- scratch (device globals; no allocs) -------------
__device__ float g_x  [MQ  * DIM];
__device__ float g_t  [MQ  * DIM];

// fp16 activations
__device__ __half g_xh [MQ * DIM];
__device__ __half g_eh [MKV * DIM];
__device__ __half g_Qh [MQ * HE];
__device__ __half g_KVh[MKV * NKV];
__device__ __half g_Oh [MQ * HE];
__device__ __half g_Hh [MQ * HID];

// fp16 weights, repacked to [N][K] per block
__device__ __half g_wq [NB*HE*DIM];
__device__ __half g_wkv[NB*NKV*DIM];
__device__ __half g_wo [NB*DIM*HE];
__device__ __half g_w1 [NB*HID*DIM];
__device__ __half g_w2 [NB*DIM*HID];

// ------------------------- helpers ----------------------------------------
__device__ __forceinline__ float gelu_exact(float v)
{
    return 0.5f * v * (1.0f + erff(v * 0.70710678118654752f));
}
__device__ __forceinline__ uint32_t smaddr(const void* p)
{
    return (uint32_t)__cvta_generic_to_shared(p);
}
__device__ __forceinline__ void cp16(uint32_t dst, const void* src)
{
    asm volatile("cp.async.cg.shared.global [%0], [%1], 16;" :: "r"(dst), "l"(src));
}
__device__ __forceinline__ void ldsm4(uint32_t a[4], uint32_t addr)
{
    asm volatile("ldmatrix.sync.aligned.m8n8.x4.shared.b16 {%0,%1,%2,%3}, [%4];"
                 : "=r"(a[0]), "=r"(a[1]), "=r"(a[2]), "=r"(a[3]) : "r"(addr));
}
__device__ __forceinline__ void mma16816(float c[4], const uint32_t a[4],
                                         uint32_t b0, uint32_t b1)
{
    asm volatile(
        "mma.sync.aligned.m16n8k16.row.col.f32.f16.f16.f32 "
        "{%0,%1,%2,%3}, {%4,%5,%6,%7}, {%8,%9}, {%0,%1,%2,%3};"
        : "+f"(c[0]), "+f"(c[1]), "+f"(c[2]), "+f"(c[3])
        : "r"(a[0]), "r"(a[1]), "r"(a[2]), "r"(a[3]), "r"(b0), "r"(b1));
}
__device__ __forceinline__ uint32_t pack_h2(float x, float y)
{
    __half2 h = __floats2half2_rn(x, y);
    return *(uint32_t*)&h;
}

// ------------------------- repack kernels ----------------------------------
__global__ void repack_qkv(const float* __restrict__ w, __half* __restrict__ o)
{
    int idx = blockIdx.x * blockDim.x + threadIdx.x;
    const int total = NB * HE * DIM;
    if (idx >= total) return;
    int i = idx / (HE * DIM);
    int r = idx % (HE * DIM);
    int n = r / DIM, d = r % DIM;
    int h = n >> 5, e = n & 31;
    o[idx] = __float2half(w[(((long)i * HEADS + h) * DIM + d) * EHD + e]);
}
__global__ void repack_kv(const float* __restrict__ wk, const float* __restrict__ wv,
                          __half* __restrict__ o)
{
    int idx = blockIdx.x * blockDim.x + threadIdx.x;
    const int total = NB * NKV * DIM;
    if (idx >= total) return;
    int i = idx / (NKV * DIM);
    int r = idx % (NKV * DIM);
    int n = r / DIM, d = r % DIM;
    const float* src = (n < HE) ? wk : wv;
    int nn = (n < HE) ? n : n - HE;
    int h = nn >> 5, e = nn & 31;
    o[idx] = __float2half(src[(((long)i * HEADS + h) * DIM + d) * EHD + e]);
}
__global__ void repack_wo(const float* __restrict__ w, __half* __restrict__ o)
{
    int idx = blockIdx.x * blockDim.x + threadIdx.x;
    const int total = NB * DIM * HE;
    if (idx >= total) return;
    int i = idx / (DIM * HE);
    int r = idx % (DIM * HE);
    int n = r / HE, k = r % HE;
    o[idx] = __float2half(w[((long)i * HE + k) * DIM + n]);
}
__global__ void repack_ffn(const float* __restrict__ w, __half* __restrict__ o,
                           int Kd, int Nd)
{
    int idx = blockIdx.x * blockDim.x + threadIdx.x;
    const int total = NB * Kd * Nd;
    if (idx >= total) return;
    int i = idx / (Nd * Kd);
    int r = idx % (Nd * Kd);
    int n = r / Kd, k = r % Kd;
    o[idx] = __float2half(w[((long)i * Kd + k) * Nd + n]);
}

__global__ void cvt4_kernel(const float* __restrict__ x,
                            __half* __restrict__ h, int n4)
{
    int i = blockIdx.x * blockDim.x + threadIdx.x;
    if (i >= n4) return;
    float4 v = ((const float4*)x)[i];
    __half2* H = (__half2*)(h + 4*(long)i);
    H[0] = __floats2half2_rn(v.x, v.y);
    H[1] = __floats2half2_rn(v.z, v.w);
}

__global__ void init_x_kernel(const float* __restrict__ pos, float* __restrict__ x,
                              __half* __restrict__ xh)
{
    int idx = blockIdx.x * blockDim.x + threadIdx.x;
    const int total = MQ * DIM;
    if (idx >= total) return;
    int rowq = (idx / DIM) % LQ;
    int d    = idx % DIM;
    float v = pos[rowq * DIM + d];
    x[idx] = v;
    xh[idx] = __float2half(v);
}

// ------------------------- pipelined tensor-core GEMM ----------------------
// C[M,N] = A[M,K] @ W[N,K]^T, all fp16 operands, fp32 accum.
// mode 0: fp32   mode 1: GELU->fp16   mode 2: +R fp32   mode 3: fp16
#define KS 32
#define LDSS 40
#define TILE_E (128 * LDSS)
#define STAGE_E (2 * TILE_E)          // A, B
#define GEMM_SMEM (2 * STAGE_E * 2)   // 2 stages, bytes (40960)

__global__ void __launch_bounds__(256, 2) mma_gemm(
    const __half* __restrict__ A, const __half* __restrict__ B,
    const float* __restrict__ R, float* __restrict__ C,
    __half* __restrict__ Ch,
    int M, int N, int K, int mode)
{
    extern __shared__ __half smem[];
    const uint32_t sbase = smaddr(smem);

    const int t    = threadIdx.x;
    const int lane = t & 31;
    const int warp = t >> 5;
    const int wm   = (warp & 1) * 64;
    const int wn   = (warp >> 1) * 32;
    const long bm  = (long)blockIdx.x * 128;
    const long bn  = (long)blockIdx.y * 128;

    const int lrow = lane & 15;
    const int lcol = (lane >> 4) * 8;

    float c[4][4][4];
#pragma unroll
    for (int a = 0; a < 4; ++a)
#pragma unroll
        for (int b = 0; b < 4; ++b)
#pragma unroll
            for (int d = 0; d < 4; ++d) c[a][b][d] = 0.f;

    const int T = K / KS;

    auto load_stage = [&](int buf, int k0) {
        uint32_t sb = sbase + (uint32_t)(buf * STAGE_E) * 2;
#pragma unroll
        for (int i = 0; i < 2; ++i) {
            int lin = t + i * 256;
            int row = lin >> 2;
            int ce  = (lin & 3) * 8;
            uint32_t off = (uint32_t)(row * LDSS + ce) * 2;
            cp16(sb + off,              A + (bm + row) * (long)K + k0 + ce);
            cp16(sb + TILE_E * 2 + off, B + (bn + row) * (long)K + k0 + ce);
        }
        asm volatile("cp.async.commit_group;");
    };

    load_stage(0, 0);

    for (int s = 0; s < T; ++s) {
        const int cur = s & 1;
        if (s + 1 < T) {
            load_stage(cur ^ 1, (s + 1) * KS);
            asm volatile("cp.async.wait_group 1;");
        } else {
            asm volatile("cp.async.wait_group 0;");
        }
        __syncthreads();

        const __half* sA = smem + cur * STAGE_E;
        const __half* sB = sA + TILE_E;

#pragma unroll
        for (int kk = 0; kk < KS; kk += 16) {
            uint32_t ah[4][4];
#pragma unroll
            for (int mt = 0; mt < 4; ++mt) {
                int r = (wm + mt * 16 + lrow) * LDSS + kk + lcol;
                ldsm4(ah[mt], smaddr(&sA[r]));
            }
#pragma unroll
            for (int ng = 0; ng < 2; ++ng) {
                uint32_t bh[4];
                int r = (wn + ng * 16 + lrow) * LDSS + kk + lcol;
                ldsm4(bh, smaddr(&sB[r]));
#pragma unroll
                for (int hf = 0; hf < 2; ++hf) {
                    int nt = ng * 2 + hf;
                    uint32_t b0 = bh[hf], b1 = bh[hf + 2];
#pragma unroll
                    for (int mt = 0; mt < 4; ++mt)
                        mma16816(c[mt][nt], ah[mt], b0, b1);
                }
            }
        }
        __syncthreads();
    }

    // ---- epilogue ----
#pragma unroll
    for (int mt = 0; mt < 4; ++mt) {
        long row0e = bm + wm + mt * 16 + (lane >> 2);
#pragma unroll
        for (int nt = 0; nt < 4; ++nt) {
            int col = (int)bn + wn + nt * 8 + (lane & 3) * 2;
#pragma unroll
            for (int hfr = 0; hfr < 2; ++hfr) {
                long row = row0e + hfr * 8;
                float vx = c[mt][nt][hfr * 2 + 0];
                float vy = c[mt][nt][hfr * 2 + 1];
                if (mode == 2) {
                    float2 r = *(const float2*)&R[row * N + col];
                    float2 v; v.x = vx + r.x; v.y = vy + r.y;
                    *(float2*)&C[row * N + col] = v;
                } else if (mode == 1) {
                    vx = gelu_exact(vx); vy = gelu_exact(vy);
                    *(__half2*)&Ch[row * N + col] = __floats2half2_rn(vx, vy);
                } else if (mode == 3) {
                    *(__half2*)&Ch[row * N + col] = __floats2half2_rn(vx, vy);
                } else {
                    float2 v; v.x = vx; v.y = vy;
                    *(float2*)&C[row * N + col] = v;
                }
            }
        }
    }
}

// ------------------------- LayerNorm (row per CTA), fused fp16 out ---------
__global__ void __launch_bounds__(256) ln_kernel(
    const float* __restrict__ in, const float* __restrict__ gg,
    const float* __restrict__ bb, float* __restrict__ out,
    __half* __restrict__ oh)
{
    const int row = blockIdx.x;
    const float* x = in + (long)row * DIM;
    const int t = threadIdx.x;

    float v0 = x[t], v1 = x[t + 256], v2 = x[t + 512];
    float s  = v0 + v1 + v2;
    float ss = v0 * v0 + v1 * v1 + v2 * v2;

    __shared__ float sh[16];
#pragma unroll
    for (int o = 16; o; o >>= 1) {
        s  += __shfl_xor_sync(0xffffffffu, s, o);
        ss += __shfl_xor_sync(0xffffffffu, ss, o);
    }
    int w = t >> 5, l = t & 31;
    if (l == 0) { sh[w] = s; sh[w + 8] = ss; }
    __syncthreads();
    s  = sh[0] + sh[1] + sh[2] + sh[3] + sh[4] + sh[5] + sh[6] + sh[7];
    ss = sh[8] + sh[9] + sh[10] + sh[11] + sh[12] + sh[13] + sh[14] + sh[15];

    const float mean = s * (1.0f / DIM);
    const float var  = ss * (1.0f / DIM) - mean * mean;
    const float inv  = rsqrtf(var + 1e-6f);

    float* o = out + (long)row * DIM;
    __half* ph = oh + (long)row * DIM;
#pragma unroll
    for (int j = 0; j < 3; ++j) {
        int idx = t + j * 256;
        float vv = (j == 0 ? v0 : (j == 1 ? v1 : v2));
        float r = (vv - mean) * inv * gg[idx] + bb[idx];
        o[idx] = r;
        ph[idx] = __float2half(r);
    }
}

// ------------------------- tensor-core attention ---------------------------
// one CTA per (b,h). Q[64x32], K[512x32] fp16; S fp32 smem; V^T [32x512] fp16.
#define ALD 40            // fp16 stride for Q/K rows (32+8)
#define VLD 520           // fp16 stride for V^T rows (512+8)
#define SPW 516           // fp32 stride for S rows
#define OFF_K  2560       // half offset of K
#define OFF_VT 23040      // half offset of V^T
#define OFF_P  79360      // BYTE offset of S/P (fp32)
#define ATTN_SMEM (OFF_P + 64 * SPW * 4)   // 211456 bytes

__global__ void __launch_bounds__(256) attn_kernel(
    const __half* __restrict__ Q, const __half* __restrict__ KV,
    __half* __restrict__ Oh)
{
    extern __shared__ char smc[];
    __half* sQ  = (__half*)smc;
    __half* sK  = (__half*)smc + OFF_K;
    __half* sVt = (__half*)smc + OFF_VT;
    float*  sP  = (float*)(smc + OFF_P);

    const int t = threadIdx.x;
    const int lane = t & 31;
    const int warp = t >> 5;
    const int b = blockIdx.x / HEADS;
    const int h = blockIdx.x % HEADS;
    const float scale = 0.03608439182435161f;  // 768^-0.5

    const __half* Qg = Q  + ((long)b * LQ) * HE  + h * EHD;
    const __half* Kg = KV + ((long)b * SK) * NKV + h * EHD;
    const __half* Vg = Kg + HE;

    {
        int row = t >> 2, ch = (t & 3) * 8;
        *(uint4*)&sQ[row * ALD + ch] = *(const uint4*)&Qg[(long)row * HE + ch];
    }
#pragma unroll
    for (int i = 0; i < 8; ++i) {
        int lin = t + i * 256;
        int row = lin >> 2, ch = (lin & 3) * 8;
        *(uint4*)&sK[row * ALD + ch] = *(const uint4*)&Kg[(long)row * NKV + ch];
    }
#pragma unroll
    for (int i = 0; i < 8; ++i) {
        int lin = t + i * 256;
        int tok = lin >> 2, e0 = (lin & 3) * 8;
        uint4 v = *(const uint4*)&Vg[(long)tok * NKV + e0];
        const __half* hv = (const __half*)&v;
#pragma unroll
        for (int j = 0; j < 8; ++j)
            sVt[(e0 + j) * VLD + tok] = hv[j];
    }
    __syncthreads();

    const int lrow = lane & 15;
    const int lcol = (lane >> 4) * 8;
    const int r  = lane >> 2;
    const int cc = (lane & 3) * 2;

    // ---- phase 1: S = Q @ K^T * scale ----
    {
        const int wm  = (warp & 3) * 16;
        const int wn0 = (warp >> 2) * 256;
        uint32_t aq[2][4];
#pragma unroll
        for (int k2 = 0; k2 < 2; ++k2)
            ldsm4(aq[k2], smaddr(&sQ[(wm + lrow) * ALD + k2 * 16 + lcol]));

#pragma unroll 4
        for (int ng = 0; ng < 16; ++ng) {
            float c0[4] = {0,0,0,0}, c1[4] = {0,0,0,0};
#pragma unroll
            for (int k2 = 0; k2 < 2; ++k2) {
                uint32_t bk[4];
                ldsm4(bk, smaddr(&sK[(wn0 + ng * 16 + lrow) * ALD + k2 * 16 + lcol]));
                mma16816(c0, aq[k2], bk[0], bk[2]);
                mma16816(c1, aq[k2], bk[1], bk[3]);
            }
            int col = wn0 + ng * 16;
            float2 v;
            v.x = c0[0] * scale; v.y = c0[1] * scale;
            *(float2*)&sP[(wm + r) * SPW + col + cc] = v;
            v.x = c0[2] * scale; v.y = c0[3] * scale;
            *(float2*)&sP[(wm + r + 8) * SPW + col + cc] = v;
            v.x = c1[0] * scale; v.y = c1[1] * scale;
            *(float2*)&sP[(wm + r) * SPW + col + 8 + cc] = v;
            v.x = c1[2] * scale; v.y = c1[3] * scale;
            *(float2*)&sP[(wm + r + 8) * SPW + col + 8 + cc] = v;
        }
    }
    __syncthreads();

    // ---- phase 2: softmax ----
    {
        const int q = t >> 2, part = t & 3;
        float* row = sP + q * SPW;
        const int s_lo = part * 128, s_hi = s_lo + 128;
        float mx = -1e30f;
        for (int s = s_lo; s < s_hi; ++s) mx = fmaxf(mx, row[s]);
        mx = fmaxf(mx, __shfl_xor_sync(0xffffffffu, mx, 1));
        mx = fmaxf(mx, __shfl_xor_sync(0xffffffffu, mx, 2));
        float sum = 0.f;
        for (int s = s_lo; s < s_hi; ++s) {
            float ev = __expf(row[s] - mx);
            row[s] = ev;
            sum += ev;
        }
        sum += __shfl_xor_sync(0xffffffffu, sum, 1);
        sum += __shfl_xor_sync(0xffffffffu, sum, 2);
        float inv = 1.0f / sum;
        for (int s = s_lo; s < s_hi; ++s) row[s] *= inv;
    }
    __syncthreads();

    // ---- phase 3: O = P @ V ----
    {
        const int wm = (warp & 3) * 16;
        const int wn = (warp >> 2) * 16;
        float o0[4] = {0,0,0,0}, o1[4] = {0,0,0,0};

#pragma unroll 4
        for (int kk = 0; kk < SK; kk += 16) {
            const float* p0 = &sP[(wm + r) * SPW + kk];
            const float* p1 = &sP[(wm + r + 8) * SPW + kk];
            float2 q00 = *(const float2*)&p0[cc];
            float2 q10 = *(const float2*)&p1[cc];
            float2 q01 = *(const float2*)&p0[cc + 8];
            float2 q11 = *(const float2*)&p1[cc + 8];
            uint32_t a[4];
            a[0] = pack_h2(q00.x, q00.y);
            a[1] = pack_h2(q10.x, q10.y);
            a[2] = pack_h2(q01.x, q01.y);
            a[3] = pack_h2(q11.x, q11.y);
            uint32_t bv[4];
            ldsm4(bv, smaddr(&sVt[(wn + lrow) * VLD + kk + lcol]));
            mma16816(o0, a, bv[0], bv[2]);
            mma16816(o1, a, bv[1], bv[3]);
        }

        long ob = ((long)b * LQ) * HE + h * EHD;
        *(__half2*)&Oh[ob + (long)(wm + r) * HE + wn + cc]
            = __floats2half2_rn(o0[0], o0[1]);
        *(__half2*)&Oh[ob + (long)(wm + r + 8) * HE + wn + cc]
            = __floats2half2_rn(o0[2], o0[3]);
        *(__half2*)&Oh[ob + (long)(wm + r) * HE + wn + 8 + cc]
            = __floats2half2_rn(o1[0], o1[1]);
        *(__half2*)&Oh[ob + (long)(wm + r + 8) * HE + wn + 8 + cc]
            = __floats2half2_rn(o1[2], o1[3]);
    }
}

// ------------------------- driver ------------------------------------------
extern "C" void kernel_launch(void* const* d_in, const int* in_sizes, int n_in,
                              void* d_out, int out_size)
{
    const float* enc  = (const float*)d_in[0];
    const float* pos  = (const float*)d_in[1];
    const float* wq   = (const float*)d_in[2];
    const float* wk   = (const float*)d_in[3];
    const float* wv   = (const float*)d_in[4];
    const float* wo   = (const float*)d_in[5];
    const float* ln1g = (const float*)d_in[6];
    const float* ln1b = (const float*)d_in[7];
    const float* ln2g = (const float*)d_in[8];
    const float* ln2b = (const float*)d_in[9];
    const float* w1   = (const float*)d_in[10];
    const float* w2   = (const float*)d_in[11];

    float *x, *tmp;
    cudaGetSymbolAddress((void**)&x,   g_x);
    cudaGetSymbolAddress((void**)&tmp, g_t);

    __half *xh,*eh,*Qh,*KVh,*Oh,*Hh;
    cudaGetSymbolAddress((void**)&xh,  g_xh);
    cudaGetSymbolAddress((void**)&eh,  g_eh);
    cudaGetSymbolAddress((void**)&Qh,  g_Qh);
    cudaGetSymbolAddress((void**)&KVh, g_KVh);
    cudaGetSymbolAddress((void**)&Oh,  g_Oh);
    cudaGetSymbolAddress((void**)&Hh,  g_Hh);

    __half *wqp,*wkvp,*wop,*w1p,*w2p;
    cudaGetSymbolAddress((void**)&wqp,  g_wq);
    cudaGetSymbolAddress((void**)&wkvp, g_wkv);
    cudaGetSymbolAddress((void**)&wop,  g_wo);
    cudaGetSymbolAddress((void**)&w1p,  g_w1);
    cudaGetSymbolAddress((void**)&w2p,  g_w2);

    cudaFuncSetAttribute(attn_kernel, cudaFuncAttributeMaxDynamicSharedMemorySize,
                         ATTN_SMEM);
    cudaFuncSetAttribute(mma_gemm, cudaFuncAttributeMaxDynamicSharedMemorySize,
                         GEMM_SMEM);

    {
        int n = NB * HE * DIM;
        repack_qkv<<<(n + 255) / 256, 256>>>(wq, wqp);
        repack_wo <<<(n + 255) / 256, 256>>>(wo, wop);
        int nkv = NB * NKV * DIM;
        repack_kv<<<(nkv + 255) / 256, 256>>>(wk, wv, wkvp);
        int nf = NB * DIM * HID;
        repack_ffn<<<(nf + 255) / 256, 256>>>(w1, w1p, DIM, HID);
        repack_ffn<<<(nf + 255) / 256, 256>>>(w2, w2p, HID, DIM);
    }
    init_x_kernel<<<(MQ * DIM + 255) / 256, 256>>>(pos, x, xh);
    cvt4_kernel<<<(MKV * DIM / 4 + 255) / 256, 256>>>(enc, eh, MKV * DIM / 4);

    dim3 gQ  (MQ  / 128, HE  / 128);  // 32 x 3
    dim3 gKV (MKV / 128, NKV / 128);  // 256 x 6
    dim3 gO  (MQ  / 128, DIM / 128);  // 32 x 6
    dim3 gF1 (MQ  / 128, HID / 128);  // 32 x 24
    dim3 gF2 (MQ  / 128, DIM / 128);  // 32 x 6

    for (int i = 0; i < NB; ++i) {
        const long woff   = (long)i * DIM * HE;
        const long wkvoff = (long)i * DIM * NKV;
        const long w1off  = (long)i * DIM * HID;
        const long w2off  = (long)i * HID * DIM;

        mma_gemm<<<gQ,  256, GEMM_SMEM>>>(xh, wqp + woff,
                                          nullptr, nullptr, Qh, MQ,  HE, DIM, 3);
        mma_gemm<<<gKV, 256, GEMM_SMEM>>>(eh, wkvp + wkvoff,
                                          nullptr, nullptr, KVh, MKV, NKV, DIM, 3);

        attn_kernel<<<BATCH * HEADS, 256, ATTN_SMEM>>>(Qh, KVh, Oh);

        mma_gemm<<<gO, 256, GEMM_SMEM>>>(Oh, wop + woff,
                                         x, tmp, nullptr, MQ, DIM, HE, 2);
        ln_kernel<<<MQ, 256>>>(tmp, ln1g + i * DIM, ln1b + i * DIM, x, xh);

        mma_gemm<<<gF1, 256, GEMM_SMEM>>>(xh, w1p + w1off,
                                          nullptr, nullptr, Hh, MQ, HID, DIM, 1);
        mma_gemm<<<gF2, 256, GEMM_SMEM>>>(Hh, w2p + w2off,
                                          x, tmp, nullptr, MQ, DIM, HID, 2);
        ln_kernel<<<MQ, 256>>>(tmp, ln2g + i * DIM, ln2b + i * DIM,
                               (i == NB - 1) ? (float*)d_out : x, xh);
    }
}

// round 16
// speedup vs baseline: 1.0050x; 1.0002x over previous
#include <cuda_runtime.h>
#include <cuda_fp16.h>
#include <math.h>
#include <stdint.h>

// Shapes (fixed by the problem)
#define NB 6
#define HEADS 12
#define DIM 768
#define EHD 32
#define HE 384
#define NKV 768          // fused K|V projection width
#define LQ 64
#define SK 512
#define BATCH 64
#define HID 3072
#define MQ (BATCH*LQ)   // 4096
#define MKV (BATCH*SK)  // 32768

// ------------------------- scratch (device globals; no allocs) -------------
__device__ float g_x  [MQ  * DIM];
__device__ float g_t  [MQ  * DIM];

// fp16 activations
__device__ __half g_xh [MQ * DIM];
__device__ __half g_eh [MKV * DIM];
__device__ __half g_Qh [MQ * HE];
__device__ __half g_KVh[MKV * NKV];
__device__ __half g_Oh [MQ * HE];
__device__ __half g_Hh [MQ * HID];

// fp16 weights, repacked to [N][K] per block
__device__ __half g_wq [NB*HE*DIM];
__device__ __half g_wkv[NB*NKV*DIM];
__device__ __half g_wo [NB*DIM*HE];
__device__ __half g_w1 [NB*HID*DIM];
__device__ __half g_w2 [NB*DIM*HID];

// ------------------------- helpers ----------------------------------------
__device__ __forceinline__ float gelu_exact(float v)
{
    return 0.5f * v * (1.0f + erff(v * 0.70710678118654752f));
}
__device__ __forceinline__ uint32_t smaddr(const void* p)
{
    return (uint32_t)__cvta_generic_to_shared(p);
}
__device__ __forceinline__ void cp16(uint32_t dst, const void* src)
{
    asm volatile("cp.async.cg.shared.global [%0], [%1], 16;" :: "r"(dst), "l"(src));
}
__device__ __forceinline__ void ldsm4(uint32_t a[4], uint32_t addr)
{
    asm volatile("ldmatrix.sync.aligned.m8n8.x4.shared.b16 {%0,%1,%2,%3}, [%4];"
                 : "=r"(a[0]), "=r"(a[1]), "=r"(a[2]), "=r"(a[3]) : "r"(addr));
}
__device__ __forceinline__ void mma16816(float c[4], const uint32_t a[4],
                                         uint32_t b0, uint32_t b1)
{
    asm volatile(
        "mma.sync.aligned.m16n8k16.row.col.f32.f16.f16.f32 "
        "{%0,%1,%2,%3}, {%4,%5,%6,%7}, {%8,%9}, {%0,%1,%2,%3};"
        : "+f"(c[0]), "+f"(c[1]), "+f"(c[2]), "+f"(c[3])
        : "r"(a[0]), "r"(a[1]), "r"(a[2]), "r"(a[3]), "r"(b0), "r"(b1));
}
__device__ __forceinline__ uint32_t pack_h2(float x, float y)
{
    __half2 h = __floats2half2_rn(x, y);
    return *(uint32_t*)&h;
}

// ------------------------- repack kernels ----------------------------------
__global__ void repack_qkv(const float* __restrict__ w, __half* __restrict__ o)
{
    int idx = blockIdx.x * blockDim.x + threadIdx.x;
    const int total = NB * HE * DIM;
    if (idx >= total) return;
    int i = idx / (HE * DIM);
    int r = idx % (HE * DIM);
    int n = r / DIM, d = r % DIM;
    int h = n >> 5, e = n & 31;
    o[idx] = __float2half(w[(((long)i * HEADS + h) * DIM + d) * EHD + e]);
}
__global__ void repack_kv(const float* __restrict__ wk, const float* __restrict__ wv,
                          __half* __restrict__ o)
{
    int idx = blockIdx.x * blockDim.x + threadIdx.x;
    const int total = NB * NKV * DIM;
    if (idx >= total) return;
    int i = idx / (NKV * DIM);
    int r = idx % (NKV * DIM);
    int n = r / DIM, d = r % DIM;
    const float* src = (n < HE) ? wk : wv;
    int nn = (n < HE) ? n : n - HE;
    int h = nn >> 5, e = nn & 31;
    o[idx] = __float2half(src[(((long)i * HEADS + h) * DIM + d) * EHD + e]);
}
__global__ void repack_wo(const float* __restrict__ w, __half* __restrict__ o)
{
    int idx = blockIdx.x * blockDim.x + threadIdx.x;
    const int total = NB * DIM * HE;
    if (idx >= total) return;
    int i = idx / (DIM * HE);
    int r = idx % (DIM * HE);
    int n = r / HE, k = r % HE;
    o[idx] = __float2half(w[((long)i * HE + k) * DIM + n]);
}
__global__ void repack_ffn(const float* __restrict__ w, __half* __restrict__ o,
                           int Kd, int Nd)
{
    int idx = blockIdx.x * blockDim.x + threadIdx.x;
    const int total = NB * Kd * Nd;
    if (idx >= total) return;
    int i = idx / (Nd * Kd);
    int r = idx % (Nd * Kd);
    int n = r / Kd, k = r % Kd;
    o[idx] = __float2half(w[((long)i * Kd + k) * Nd + n]);
}

__global__ void cvt4_kernel(const float* __restrict__ x,
                            __half* __restrict__ h, int n4)
{
    int i = blockIdx.x * blockDim.x + threadIdx.x;
    if (i >= n4) return;
    float4 v = ((const float4*)x)[i];
    __half2* H = (__half2*)(h + 4*(long)i);
    H[0] = __floats2half2_rn(v.x, v.y);
    H[1] = __floats2half2_rn(v.z, v.w);
}

__global__ void init_x_kernel(const float* __restrict__ pos, float* __restrict__ x,
                              __half* __restrict__ xh)
{
    int idx = blockIdx.x * blockDim.x + threadIdx.x;
    const int total = MQ * DIM;
    if (idx >= total) return;
    int rowq = (idx / DIM) % LQ;
    int d    = idx % DIM;
    float v = pos[rowq * DIM + d];
    x[idx] = v;
    xh[idx] = __float2half(v);
}

// ------------------------- pipelined tensor-core GEMM ----------------------
// C[M,N] = A[M,K] @ W[N,K]^T, all fp16 operands, fp32 accum.
// mode 0: fp32   mode 1: GELU->fp16   mode 2: +R fp32   mode 3: fp16
#define KS 32
#define LDSS 40
#define TILE_E (128 * LDSS)
#define STAGE_E (2 * TILE_E)          // A, B
#define GEMM_SMEM (2 * STAGE_E * 2)   // 2 stages, bytes (40960)

__global__ void __launch_bounds__(256, 2) mma_gemm(
    const __half* __restrict__ A, const __half* __restrict__ B,
    const float* __restrict__ R, float* __restrict__ C,
    __half* __restrict__ Ch,
    int M, int N, int K, int mode)
{
    extern __shared__ __half smem[];
    const uint32_t sbase = smaddr(smem);

    const int t    = threadIdx.x;
    const int lane = t & 31;
    const int warp = t >> 5;
    const int wm   = (warp & 1) * 64;
    const int wn   = (warp >> 1) * 32;
    const long bm  = (long)blockIdx.x * 128;
    const long bn  = (long)blockIdx.y * 128;

    const int lrow = lane & 15;
    const int lcol = (lane >> 4) * 8;

    float c[4][4][4];
#pragma unroll
    for (int a = 0; a < 4; ++a)
#pragma unroll
        for (int b = 0; b < 4; ++b)
#pragma unroll
            for (int d = 0; d < 4; ++d) c[a][b][d] = 0.f;

    const int T = K / KS;

    auto load_stage = [&](int buf, int k0) {
        uint32_t sb = sbase + (uint32_t)(buf * STAGE_E) * 2;
#pragma unroll
        for (int i = 0; i < 2; ++i) {
            int lin = t + i * 256;
            int row = lin >> 2;
            int ce  = (lin & 3) * 8;
            uint32_t off = (uint32_t)(row * LDSS + ce) * 2;
            cp16(sb + off,              A + (bm + row) * (long)K + k0 + ce);
            cp16(sb + TILE_E * 2 + off, B + (bn + row) * (long)K + k0 + ce);
        }
        asm volatile("cp.async.commit_group;");
    };

    load_stage(0, 0);

    for (int s = 0; s < T; ++s) {
        const int cur = s & 1;
        if (s + 1 < T) {
            load_stage(cur ^ 1, (s + 1) * KS);
            asm volatile("cp.async.wait_group 1;");
        } else {
            asm volatile("cp.async.wait_group 0;");
        }
        __syncthreads();

        const __half* sA = smem + cur * STAGE_E;
        const __half* sB = sA + TILE_E;

#pragma unroll
        for (int kk = 0; kk < KS; kk += 16) {
            uint32_t ah[4][4];
#pragma unroll
            for (int mt = 0; mt < 4; ++mt) {
                int r = (wm + mt * 16 + lrow) * LDSS + kk + lcol;
                ldsm4(ah[mt], smaddr(&sA[r]));
            }
#pragma unroll
            for (int ng = 0; ng < 2; ++ng) {
                uint32_t bh[4];
                int r = (wn + ng * 16 + lrow) * LDSS + kk + lcol;
                ldsm4(bh, smaddr(&sB[r]));
#pragma unroll
                for (int hf = 0; hf < 2; ++hf) {
                    int nt = ng * 2 + hf;
                    uint32_t b0 = bh[hf], b1 = bh[hf + 2];
#pragma unroll
                    for (int mt = 0; mt < 4; ++mt)
                        mma16816(c[mt][nt], ah[mt], b0, b1);
                }
            }
        }
        __syncthreads();
    }

    // ---- epilogue ----
#pragma unroll
    for (int mt = 0; mt < 4; ++mt) {
        long row0e = bm + wm + mt * 16 + (lane >> 2);
#pragma unroll
        for (int nt = 0; nt < 4; ++nt) {
            int col = (int)bn + wn + nt * 8 + (lane & 3) * 2;
#pragma unroll
            for (int hfr = 0; hfr < 2; ++hfr) {
                long row = row0e + hfr * 8;
                float vx = c[mt][nt][hfr * 2 + 0];
                float vy = c[mt][nt][hfr * 2 + 1];
                if (mode == 2) {
                    float2 r = *(const float2*)&R[row * N + col];
                    float2 v; v.x = vx + r.x; v.y = vy + r.y;
                    *(float2*)&C[row * N + col] = v;
                } else if (mode == 1) {
                    vx = gelu_exact(vx); vy = gelu_exact(vy);
                    *(__half2*)&Ch[row * N + col] = __floats2half2_rn(vx, vy);
                } else if (mode == 3) {
                    *(__half2*)&Ch[row * N + col] = __floats2half2_rn(vx, vy);
                } else {
                    float2 v; v.x = vx; v.y = vy;
                    *(float2*)&C[row * N + col] = v;
                }
            }
        }
    }
}

// ------------------------- LayerNorm (row per CTA), fused fp16 out ---------
__global__ void __launch_bounds__(256) ln_kernel(
    const float* __restrict__ in, const float* __restrict__ gg,
    const float* __restrict__ bb, float* __restrict__ out,
    __half* __restrict__ oh)
{
    const int row = blockIdx.x;
    const float* x = in + (long)row * DIM;
    const int t = threadIdx.x;

    float v0 = x[t], v1 = x[t + 256], v2 = x[t + 512];
    float s  = v0 + v1 + v2;
    float ss = v0 * v0 + v1 * v1 + v2 * v2;

    __shared__ float sh[16];
#pragma unroll
    for (int o = 16; o; o >>= 1) {
        s  += __shfl_xor_sync(0xffffffffu, s, o);
        ss += __shfl_xor_sync(0xffffffffu, ss, o);
    }
    int w = t >> 5, l = t & 31;
    if (l == 0) { sh[w] = s; sh[w + 8] = ss; }
    __syncthreads();
    s  = sh[0] + sh[1] + sh[2] + sh[3] + sh[4] + sh[5] + sh[6] + sh[7];
    ss = sh[8] + sh[9] + sh[10] + sh[11] + sh[12] + sh[13] + sh[14] + sh[15];

    const float mean = s * (1.0f / DIM);
    const float var  = ss * (1.0f / DIM) - mean * mean;
    const float inv  = rsqrtf(var + 1e-6f);

    float* o = out + (long)row * DIM;
    __half* ph = oh + (long)row * DIM;
#pragma unroll
    for (int j = 0; j < 3; ++j) {
        int idx = t + j * 256;
        float vv = (j == 0 ? v0 : (j == 1 ? v1 : v2));
        float r = (vv - mean) * inv * gg[idx] + bb[idx];
        o[idx] = r;
        ph[idx] = __float2half(r);
    }
}

// ------------------------- tensor-core attention ---------------------------
// one CTA per (b,h). Q[64x32], K[512x32] fp16; S fp32 smem; V^T [32x512] fp16.
#define ALD 40            // fp16 stride for Q/K rows (32+8)
#define VLD 520           // fp16 stride for V^T rows (512+8)
#define SPW 516           // fp32 stride for S rows
#define OFF_K  2560       // half offset of K
#define OFF_VT 23040      // half offset of V^T
#define OFF_P  79360      // BYTE offset of S/P (fp32)
#define ATTN_SMEM (OFF_P + 64 * SPW * 4)   // 211456 bytes

__global__ void __launch_bounds__(256) attn_kernel(
    const __half* __restrict__ Q, const __half* __restrict__ KV,
    __half* __restrict__ Oh)
{
    extern __shared__ char smc[];
    __half* sQ  = (__half*)smc;
    __half* sK  = (__half*)smc + OFF_K;
    __half* sVt = (__half*)smc + OFF_VT;
    float*  sP  = (float*)(smc + OFF_P);

    const int t = threadIdx.x;
    const int lane = t & 31;
    const int warp = t >> 5;
    const int b = blockIdx.x / HEADS;
    const int h = blockIdx.x % HEADS;
    const float scale = 0.03608439182435161f;  // 768^-0.5

    const __half* Qg = Q  + ((long)b * LQ) * HE  + h * EHD;
    const __half* Kg = KV + ((long)b * SK) * NKV + h * EHD;
    const __half* Vg = Kg + HE;

    {
        int row = t >> 2, ch = (t & 3) * 8;
        *(uint4*)&sQ[row * ALD + ch] = *(const uint4*)&Qg[(long)row * HE + ch];
    }
#pragma unroll
    for (int i = 0; i < 8; ++i) {
        int lin = t + i * 256;
        int row = lin >> 2, ch = (lin & 3) * 8;
        *(uint4*)&sK[row * ALD + ch] = *(const uint4*)&Kg[(long)row * NKV + ch];
    }
#pragma unroll
    for (int i = 0; i < 8; ++i) {
        int lin = t + i * 256;
        int tok = lin >> 2, e0 = (lin & 3) * 8;
        uint4 v = *(const uint4*)&Vg[(long)tok * NKV + e0];
        const __half* hv = (const __half*)&v;
#pragma unroll
        for (int j = 0; j < 8; ++j)
            sVt[(e0 + j) * VLD + tok] = hv[j];
    }
    __syncthreads();

    const int lrow = lane & 15;
    const int lcol = (lane >> 4) * 8;
    const int r  = lane >> 2;
    const int cc = (lane & 3) * 2;

    // ---- phase 1: S = Q @ K^T * scale ----
    {
        const int wm  = (warp & 3) * 16;
        const int wn0 = (warp >> 2) * 256;
        uint32_t aq[2][4];
#pragma unroll
        for (int k2 = 0; k2 < 2; ++k2)
            ldsm4(aq[k2], smaddr(&sQ[(wm + lrow) * ALD + k2 * 16 + lcol]));

#pragma unroll 4
        for (int ng = 0; ng < 16; ++ng) {
            float c0[4] = {0,0,0,0}, c1[4] = {0,0,0,0};
#pragma unroll
            for (int k2 = 0; k2 < 2; ++k2) {
                uint32_t bk[4];
                ldsm4(bk, smaddr(&sK[(wn0 + ng * 16 + lrow) * ALD + k2 * 16 + lcol]));
                mma16816(c0, aq[k2], bk[0], bk[2]);
                mma16816(c1, aq[k2], bk[1], bk[3]);
            }
            int col = wn0 + ng * 16;
            float2 v;
            v.x = c0[0] * scale; v.y = c0[1] * scale;
            *(float2*)&sP[(wm + r) * SPW + col + cc] = v;
            v.x = c0[2] * scale; v.y = c0[3] * scale;
            *(float2*)&sP[(wm + r + 8) * SPW + col + cc] = v;
            v.x = c1[0] * scale; v.y = c1[1] * scale;
            *(float2*)&sP[(wm + r) * SPW + col + 8 + cc] = v;
            v.x = c1[2] * scale; v.y = c1[3] * scale;
            *(float2*)&sP[(wm + r + 8) * SPW + col + 8 + cc] = v;
        }
    }
    __syncthreads();

    // ---- phase 2: softmax ----
    {
        const int q = t >> 2, part = t & 3;
        float* row = sP + q * SPW;
        const int s_lo = part * 128, s_hi = s_lo + 128;
        float mx = -1e30f;
        for (int s = s_lo; s < s_hi; ++s) mx = fmaxf(mx, row[s]);
        mx = fmaxf(mx, __shfl_xor_sync(0xffffffffu, mx, 1));
        mx = fmaxf(mx, __shfl_xor_sync(0xffffffffu, mx, 2));
        float sum = 0.f;
        for (int s = s_lo; s < s_hi; ++s) {
            float ev = __expf(row[s] - mx);
            row[s] = ev;
            sum += ev;
        }
        sum += __shfl_xor_sync(0xffffffffu, sum, 1);
        sum += __shfl_xor_sync(0xffffffffu, sum, 2);
        float inv = 1.0f / sum;
        for (int s = s_lo; s < s_hi; ++s) row[s] *= inv;
    }
    __syncthreads();

    // ---- phase 3: O = P @ V ----
    {
        const int wm = (warp & 3) * 16;
        const int wn = (warp >> 2) * 16;
        float o0[4] = {0,0,0,0}, o1[4] = {0,0,0,0};

#pragma unroll 4
        for (int kk = 0; kk < SK; kk += 16) {
            const float* p0 = &sP[(wm + r) * SPW + kk];
            const float* p1 = &sP[(wm + r + 8) * SPW + kk];
            float2 q00 = *(const float2*)&p0[cc];
            float2 q10 = *(const float2*)&p1[cc];
            float2 q01 = *(const float2*)&p0[cc + 8];
            float2 q11 = *(const float2*)&p1[cc + 8];
            uint32_t a[4];
            a[0] = pack_h2(q00.x, q00.y);
            a[1] = pack_h2(q10.x, q10.y);
            a[2] = pack_h2(q01.x, q01.y);
            a[3] = pack_h2(q11.x, q11.y);
            uint32_t bv[4];
            ldsm4(bv, smaddr(&sVt[(wn + lrow) * VLD + kk + lcol]));
            mma16816(o0, a, bv[0], bv[2]);
            mma16816(o1, a, bv[1], bv[3]);
        }

        long ob = ((long)b * LQ) * HE + h * EHD;
        *(__half2*)&Oh[ob + (long)(wm + r) * HE + wn + cc]
            = __floats2half2_rn(o0[0], o0[1]);
        *(__half2*)&Oh[ob + (long)(wm + r + 8) * HE + wn + cc]
            = __floats2half2_rn(o0[2], o0[3]);
        *(__half2*)&Oh[ob + (long)(wm + r) * HE + wn + 8 + cc]
            = __floats2half2_rn(o1[0], o1[1]);
        *(__half2*)&Oh[ob + (long)(wm + r + 8) * HE + wn + 8 + cc]
            = __floats2half2_rn(o1[2], o1[3]);
    }
}

// ------------------------- driver ------------------------------------------
extern "C" void kernel_launch(void* const* d_in, const int* in_sizes, int n_in,
                              void* d_out, int out_size)
{
    const float* enc  = (const float*)d_in[0];
    const float* pos  = (const float*)d_in[1];
    const float* wq   = (const float*)d_in[2];
    const float* wk   = (const float*)d_in[3];
    const float* wv   = (const float*)d_in[4];
    const float* wo   = (const float*)d_in[5];
    const float* ln1g = (const float*)d_in[6];
    const float* ln1b = (const float*)d_in[7];
    const float* ln2g = (const float*)d_in[8];
    const float* ln2b = (const float*)d_in[9];
    const float* w1   = (const float*)d_in[10];
    const float* w2   = (const float*)d_in[11];

    float *x, *tmp;
    cudaGetSymbolAddress((void**)&x,   g_x);
    cudaGetSymbolAddress((void**)&tmp, g_t);

    __half *xh,*eh,*Qh,*KVh,*Oh,*Hh;
    cudaGetSymbolAddress((void**)&xh,  g_xh);
    cudaGetSymbolAddress((void**)&eh,  g_eh);
    cudaGetSymbolAddress((void**)&Qh,  g_Qh);
    cudaGetSymbolAddress((void**)&KVh, g_KVh);
    cudaGetSymbolAddress((void**)&Oh,  g_Oh);
    cudaGetSymbolAddress((void**)&Hh,  g_Hh);

    __half *wqp,*wkvp,*wop,*w1p,*w2p;
    cudaGetSymbolAddress((void**)&wqp,  g_wq);
    cudaGetSymbolAddress((void**)&wkvp, g_wkv);
    cudaGetSymbolAddress((void**)&wop,  g_wo);
    cudaGetSymbolAddress((void**)&w1p,  g_w1);
    cudaGetSymbolAddress((void**)&w2p,  g_w2);

    cudaFuncSetAttribute(attn_kernel, cudaFuncAttributeMaxDynamicSharedMemorySize,
                         ATTN_SMEM);
    cudaFuncSetAttribute(mma_gemm, cudaFuncAttributeMaxDynamicSharedMemorySize,
                         GEMM_SMEM);

    {
        int n = NB * HE * DIM;
        repack_qkv<<<(n + 255) / 256, 256>>>(wq, wqp);
        repack_wo <<<(n + 255) / 256, 256>>>(wo, wop);
        int nkv = NB * NKV * DIM;
        repack_kv<<<(nkv + 255) / 256, 256>>>(wk, wv, wkvp);
        int nf = NB * DIM * HID;
        repack_ffn<<<(nf + 255) / 256, 256>>>(w1, w1p, DIM, HID);
        repack_ffn<<<(nf + 255) / 256, 256>>>(w2, w2p, HID, DIM);
    }
    init_x_kernel<<<(MQ * DIM + 255) / 256, 256>>>(pos, x, xh);
    cvt4_kernel<<<(MKV * DIM / 4 + 255) / 256, 256>>>(enc, eh, MKV * DIM / 4);

    dim3 gQ  (MQ  / 128, HE  / 128);  // 32 x 3
    dim3 gKV (MKV / 128, NKV / 128);  // 256 x 6
    dim3 gO  (MQ  / 128, DIM / 128);  // 32 x 6
    dim3 gF1 (MQ  / 128, HID / 128);  // 32 x 24
    dim3 gF2 (MQ  / 128, DIM / 128);  // 32 x 6

    for (int i = 0; i < NB; ++i) {
        const long woff   = (long)i * DIM * HE;
        const long wkvoff = (long)i * DIM * NKV;
        const long w1off  = (long)i * DIM * HID;
        const long w2off  = (long)i * HID * DIM;

        mma_gemm<<<gQ,  256, GEMM_SMEM>>>(xh, wqp + woff,
                                          nullptr, nullptr, Qh, MQ,  HE, DIM, 3);
        mma_gemm<<<gKV, 256, GEMM_SMEM>>>(eh, wkvp + wkvoff,
                                          nullptr, nullptr, KVh, MKV, NKV, DIM, 3);

        attn_kernel<<<BATCH * HEADS, 256, ATTN_SMEM>>>(Qh, KVh, Oh);

        mma_gemm<<<gO, 256, GEMM_SMEM>>>(Oh, wop + woff,
                                         x, tmp, nullptr, MQ, DIM, HE, 2);
        ln_kernel<<<MQ, 256>>>(tmp, ln1g + i * DIM, ln1b + i * DIM, x, xh);

        mma_gemm<<<gF1, 256, GEMM_SMEM>>>(xh, w1p + w1off,
                                          nullptr, nullptr, Hh, MQ, HID, DIM, 1);
        mma_gemm<<<gF2, 256, GEMM_SMEM>>>(Hh, w2p + w2off,
                                          x, tmp, nullptr, MQ, DIM, HID, 2);
        ln_kernel<<<MQ, 256>>>(tmp, ln2g + i * DIM, ln2b + i * DIM,
                               (i == NB - 1) ? (float*)d_out : x, xh);
    }
}

// round 17
// speedup vs baseline: 1.0073x; 1.0024x over previous
#include <cuda_runtime.h>
#include <cuda_fp16.h>
#include <math.h>
#include <stdint.h>

// Shapes (fixed by the problem)
#define NB 6
#define HEADS 12
#define DIM 768
#define EHD 32
#define HE 384
#define NKV 768          // fused K|V projection width
#define LQ 64
#define SK 512
#define BATCH 64
#define HID 3072
#define MQ (BATCH*LQ)   // 4096
#define MKV (BATCH*SK)  // 32768

// ------------------------- scratch (device globals; no allocs) -------------
__device__ float g_x  [MQ  * DIM];
__device__ float g_t  [MQ  * DIM];

// fp16 activations
__device__ __half g_xh [MQ * DIM];
__device__ __half g_eh [MKV * DIM];
__device__ __half g_Qh [MQ * HE];
__device__ __half g_KVh[MKV * NKV];
__device__ __half g_Oh [MQ * HE];
__device__ __half g_Hh [MQ * HID];

// fp16 weights, repacked to [N][K] per block
__device__ __half g_wq [NB*HE*DIM];
__device__ __half g_wkv[NB*NKV*DIM];
__device__ __half g_wo [NB*DIM*HE];
__device__ __half g_w1 [NB*HID*DIM];
__device__ __half g_w2 [NB*DIM*HID];

// ------------------------- helpers ----------------------------------------
__device__ __forceinline__ float gelu_exact(float v)
{
    return 0.5f * v * (1.0f + erff(v * 0.70710678118654752f));
}
__device__ __forceinline__ uint32_t smaddr(const void* p)
{
    return (uint32_t)__cvta_generic_to_shared(p);
}
__device__ __forceinline__ void cp16(uint32_t dst, const void* src)
{
    asm volatile("cp.async.cg.shared.global [%0], [%1], 16;" :: "r"(dst), "l"(src));
}
__device__ __forceinline__ void ldsm4(uint32_t a[4], uint32_t addr)
{
    asm volatile("ldmatrix.sync.aligned.m8n8.x4.shared.b16 {%0,%1,%2,%3}, [%4];"
                 : "=r"(a[0]), "=r"(a[1]), "=r"(a[2]), "=r"(a[3]) : "r"(addr));
}
__device__ __forceinline__ void mma16816(float c[4], const uint32_t a[4],
                                         uint32_t b0, uint32_t b1)
{
    asm volatile(
        "mma.sync.aligned.m16n8k16.row.col.f32.f16.f16.f32 "
        "{%0,%1,%2,%3}, {%4,%5,%6,%7}, {%8,%9}, {%0,%1,%2,%3};"
        : "+f"(c[0]), "+f"(c[1]), "+f"(c[2]), "+f"(c[3])
        : "r"(a[0]), "r"(a[1]), "r"(a[2]), "r"(a[3]), "r"(b0), "r"(b1));
}
__device__ __forceinline__ uint32_t pack_h2(float x, float y)
{
    __half2 h = __floats2half2_rn(x, y);
    return *(uint32_t*)&h;
}

// ------------------------- repack kernels ----------------------------------
__global__ void repack_qkv(const float* __restrict__ w, __half* __restrict__ o)
{
    int idx = blockIdx.x * blockDim.x + threadIdx.x;
    const int total = NB * HE * DIM;
    if (idx >= total) return;
    int i = idx / (HE * DIM);
    int r = idx % (HE * DIM);
    int n = r / DIM, d = r % DIM;
    int h = n >> 5, e = n & 31;
    o[idx] = __float2half(w[(((long)i * HEADS + h) * DIM + d) * EHD + e]);
}
__global__ void repack_kv(const float* __restrict__ wk, const float* __restrict__ wv,
                          __half* __restrict__ o)
{
    int idx = blockIdx.x * blockDim.x + threadIdx.x;
    const int total = NB * NKV * DIM;
    if (idx >= total) return;
    int i = idx / (NKV * DIM);
    int r = idx % (NKV * DIM);
    int n = r / DIM, d = r % DIM;
    const float* src = (n < HE) ? wk : wv;
    int nn = (n < HE) ? n : n - HE;
    int h = nn >> 5, e = nn & 31;
    o[idx] = __float2half(src[(((long)i * HEADS + h) * DIM + d) * EHD + e]);
}
__global__ void repack_wo(const float* __restrict__ w, __half* __restrict__ o)
{
    int idx = blockIdx.x * blockDim.x + threadIdx.x;
    const int total = NB * DIM * HE;
    if (idx >= total) return;
    int i = idx / (DIM * HE);
    int r = idx % (DIM * HE);
    int n = r / HE, k = r % HE;
    o[idx] = __float2half(w[((long)i * HE + k) * DIM + n]);
}
__global__ void repack_ffn(const float* __restrict__ w, __half* __restrict__ o,
                           int Kd, int Nd)
{
    int idx = blockIdx.x * blockDim.x + threadIdx.x;
    const int total = NB * Kd * Nd;
    if (idx >= total) return;
    int i = idx / (Nd * Kd);
    int r = idx % (Nd * Kd);
    int n = r / Kd, k = r % Kd;
    o[idx] = __float2half(w[((long)i * Kd + k) * Nd + n]);
}

__global__ void cvt4_kernel(const float* __restrict__ x,
                            __half* __restrict__ h, int n4)
{
    int i = blockIdx.x * blockDim.x + threadIdx.x;
    if (i >= n4) return;
    float4 v = ((const float4*)x)[i];
    __half2* H = (__half2*)(h + 4*(long)i);
    H[0] = __floats2half2_rn(v.x, v.y);
    H[1] = __floats2half2_rn(v.z, v.w);
}

__global__ void init_x_kernel(const float* __restrict__ pos, float* __restrict__ x,
                              __half* __restrict__ xh)
{
    int idx = blockIdx.x * blockDim.x + threadIdx.x;
    const int total = MQ * DIM;
    if (idx >= total) return;
    int rowq = (idx / DIM) % LQ;
    int d    = idx % DIM;
    float v = pos[rowq * DIM + d];
    x[idx] = v;
    xh[idx] = __float2half(v);
}

// ------------------------- pipelined tensor-core GEMM ----------------------
// C[M,N] = A[M,K] @ W[N,K]^T, all fp16 operands, fp32 accum.
// mode 0: fp32   mode 1: GELU->fp16   mode 2: +R fp32   mode 3: fp16
#define KS 32
#define LDSS 40
#define TILE_E (128 * LDSS)
#define STAGE_E (2 * TILE_E)          // A, B
#define GEMM_SMEM (2 * STAGE_E * 2)   // 2 stages, bytes (40960)

__global__ void __launch_bounds__(256, 2) mma_gemm(
    const __half* __restrict__ A, const __half* __restrict__ B,
    const float* __restrict__ R, float* __restrict__ C,
    __half* __restrict__ Ch,
    int M, int N, int K, int mode)
{
    extern __shared__ __half smem[];
    const uint32_t sbase = smaddr(smem);

    const int t    = threadIdx.x;
    const int lane = t & 31;
    const int warp = t >> 5;
    const int wm   = (warp & 1) * 64;
    const int wn   = (warp >> 1) * 32;
    const long bm  = (long)blockIdx.x * 128;
    const long bn  = (long)blockIdx.y * 128;

    const int lrow = lane & 15;
    const int lcol = (lane >> 4) * 8;

    float c[4][4][4];
#pragma unroll
    for (int a = 0; a < 4; ++a)
#pragma unroll
        for (int b = 0; b < 4; ++b)
#pragma unroll
            for (int d = 0; d < 4; ++d) c[a][b][d] = 0.f;

    const int T = K / KS;

    auto load_stage = [&](int buf, int k0) {
        uint32_t sb = sbase + (uint32_t)(buf * STAGE_E) * 2;
#pragma unroll
        for (int i = 0; i < 2; ++i) {
            int lin = t + i * 256;
            int row = lin >> 2;
            int ce  = (lin & 3) * 8;
            uint32_t off = (uint32_t)(row * LDSS + ce) * 2;
            cp16(sb + off,              A + (bm + row) * (long)K + k0 + ce);
            cp16(sb + TILE_E * 2 + off, B + (bn + row) * (long)K + k0 + ce);
        }
        asm volatile("cp.async.commit_group;");
    };

    load_stage(0, 0);

    for (int s = 0; s < T; ++s) {
        const int cur = s & 1;
        if (s + 1 < T) {
            load_stage(cur ^ 1, (s + 1) * KS);
            asm volatile("cp.async.wait_group 1;");
        } else {
            asm volatile("cp.async.wait_group 0;");
        }
        __syncthreads();

        const __half* sA = smem + cur * STAGE_E;
        const __half* sB = sA + TILE_E;

#pragma unroll
        for (int kk = 0; kk < KS; kk += 16) {
            uint32_t ah[4][4];
#pragma unroll
            for (int mt = 0; mt < 4; ++mt) {
                int r = (wm + mt * 16 + lrow) * LDSS + kk + lcol;
                ldsm4(ah[mt], smaddr(&sA[r]));
            }
#pragma unroll
            for (int ng = 0; ng < 2; ++ng) {
                uint32_t bh[4];
                int r = (wn + ng * 16 + lrow) * LDSS + kk + lcol;
                ldsm4(bh, smaddr(&sB[r]));
#pragma unroll
                for (int hf = 0; hf < 2; ++hf) {
                    int nt = ng * 2 + hf;
                    uint32_t b0 = bh[hf], b1 = bh[hf + 2];
#pragma unroll
                    for (int mt = 0; mt < 4; ++mt)
                        mma16816(c[mt][nt], ah[mt], b0, b1);
                }
            }
        }
        __syncthreads();
    }

    // ---- epilogue ----
#pragma unroll
    for (int mt = 0; mt < 4; ++mt) {
        long row0e = bm + wm + mt * 16 + (lane >> 2);
#pragma unroll
        for (int nt = 0; nt < 4; ++nt) {
            int col = (int)bn + wn + nt * 8 + (lane & 3) * 2;
#pragma unroll
            for (int hfr = 0; hfr < 2; ++hfr) {
                long row = row0e + hfr * 8;
                float vx = c[mt][nt][hfr * 2 + 0];
                float vy = c[mt][nt][hfr * 2 + 1];
                if (mode == 2) {
                    float2 r = *(const float2*)&R[row * N + col];
                    float2 v; v.x = vx + r.x; v.y = vy + r.y;
                    *(float2*)&C[row * N + col] = v;
                } else if (mode == 1) {
                    vx = gelu_exact(vx); vy = gelu_exact(vy);
                    *(__half2*)&Ch[row * N + col] = __floats2half2_rn(vx, vy);
                } else if (mode == 3) {
                    *(__half2*)&Ch[row * N + col] = __floats2half2_rn(vx, vy);
                } else {
                    float2 v; v.x = vx; v.y = vy;
                    *(float2*)&C[row * N + col] = v;
                }
            }
        }
    }
}

// ------------------------- LayerNorm (row per CTA), fused fp16 out ---------
__global__ void __launch_bounds__(256) ln_kernel(
    const float* __restrict__ in, const float* __restrict__ gg,
    const float* __restrict__ bb, float* __restrict__ out,
    __half* __restrict__ oh)
{
    const int row = blockIdx.x;
    const float* x = in + (long)row * DIM;
    const int t = threadIdx.x;

    float v0 = x[t], v1 = x[t + 256], v2 = x[t + 512];
    float s  = v0 + v1 + v2;
    float ss = v0 * v0 + v1 * v1 + v2 * v2;

    __shared__ float sh[16];
#pragma unroll
    for (int o = 16; o; o >>= 1) {
        s  += __shfl_xor_sync(0xffffffffu, s, o);
        ss += __shfl_xor_sync(0xffffffffu, ss, o);
    }
    int w = t >> 5, l = t & 31;
    if (l == 0) { sh[w] = s; sh[w + 8] = ss; }
    __syncthreads();
    s  = sh[0] + sh[1] + sh[2] + sh[3] + sh[4] + sh[5] + sh[6] + sh[7];
    ss = sh[8] + sh[9] + sh[10] + sh[11] + sh[12] + sh[13] + sh[14] + sh[15];

    const float mean = s * (1.0f / DIM);
    const float var  = ss * (1.0f / DIM) - mean * mean;
    const float inv  = rsqrtf(var + 1e-6f);

    float* o = out + (long)row * DIM;
    __half* ph = oh + (long)row * DIM;
#pragma unroll
    for (int j = 0; j < 3; ++j) {
        int idx = t + j * 256;
        float vv = (j == 0 ? v0 : (j == 1 ? v1 : v2));
        float r = (vv - mean) * inv * gg[idx] + bb[idx];
        o[idx] = r;
        ph[idx] = __float2half(r);
    }
}

// ------------------------- tensor-core attention ---------------------------
// one CTA per (b,h). Q[64x32], K[512x32] fp16; S fp32 smem; V^T [32x512] fp16.
#define ALD 40            // fp16 stride for Q/K rows (32+8)
#define VLD 520           // fp16 stride for V^T rows (512+8)
#define SPW 516           // fp32 stride for S rows
#define OFF_K  2560       // half offset of K
#define OFF_VT 23040      // half offset of V^T
#define OFF_P  79360      // BYTE offset of S/P (fp32)
#define ATTN_SMEM (OFF_P + 64 * SPW * 4)   // 211456 bytes

__global__ void __launch_bounds__(256) attn_kernel(
    const __half* __restrict__ Q, const __half* __restrict__ KV,
    __half* __restrict__ Oh)
{
    extern __shared__ char smc[];
    __half* sQ  = (__half*)smc;
    __half* sK  = (__half*)smc + OFF_K;
    __half* sVt = (__half*)smc + OFF_VT;
    float*  sP  = (float*)(smc + OFF_P);

    const int t = threadIdx.x;
    const int lane = t & 31;
    const int warp = t >> 5;
    const int b = blockIdx.x / HEADS;
    const int h = blockIdx.x % HEADS;
    const float scale = 0.03608439182435161f;  // 768^-0.5

    const __half* Qg = Q  + ((long)b * LQ) * HE  + h * EHD;
    const __half* Kg = KV + ((long)b * SK) * NKV + h * EHD;
    const __half* Vg = Kg + HE;

    {
        int row = t >> 2, ch = (t & 3) * 8;
        *(uint4*)&sQ[row * ALD + ch] = *(const uint4*)&Qg[(long)row * HE + ch];
    }
#pragma unroll
    for (int i = 0; i < 8; ++i) {
        int lin = t + i * 256;
        int row = lin >> 2, ch = (lin & 3) * 8;
        *(uint4*)&sK[row * ALD + ch] = *(const uint4*)&Kg[(long)row * NKV + ch];
    }
#pragma unroll
    for (int i = 0; i < 8; ++i) {
        int lin = t + i * 256;
        int tok = lin >> 2, e0 = (lin & 3) * 8;
        uint4 v = *(const uint4*)&Vg[(long)tok * NKV + e0];
        const __half* hv = (const __half*)&v;
#pragma unroll
        for (int j = 0; j < 8; ++j)
            sVt[(e0 + j) * VLD + tok] = hv[j];
    }
    __syncthreads();

    const int lrow = lane & 15;
    const int lcol = (lane >> 4) * 8;
    const int r  = lane >> 2;
    const int cc = (lane & 3) * 2;

    // ---- phase 1: S = Q @ K^T * scale ----
    {
        const int wm  = (warp & 3) * 16;
        const int wn0 = (warp >> 2) * 256;
        uint32_t aq[2][4];
#pragma unroll
        for (int k2 = 0; k2 < 2; ++k2)
            ldsm4(aq[k2], smaddr(&sQ[(wm + lrow) * ALD + k2 * 16 + lcol]));

#pragma unroll 4
        for (int ng = 0; ng < 16; ++ng) {
            float c0[4] = {0,0,0,0}, c1[4] = {0,0,0,0};
#pragma unroll
            for (int k2 = 0; k2 < 2; ++k2) {
                uint32_t bk[4];
                ldsm4(bk, smaddr(&sK[(wn0 + ng * 16 + lrow) * ALD + k2 * 16 + lcol]));
                mma16816(c0, aq[k2], bk[0], bk[2]);
                mma16816(c1, aq[k2], bk[1], bk[3]);
            }
            int col = wn0 + ng * 16;
            float2 v;
            v.x = c0[0] * scale; v.y = c0[1] * scale;
            *(float2*)&sP[(wm + r) * SPW + col + cc] = v;
            v.x = c0[2] * scale; v.y = c0[3] * scale;
            *(float2*)&sP[(wm + r + 8) * SPW + col + cc] = v;
            v.x = c1[0] * scale; v.y = c1[1] * scale;
            *(float2*)&sP[(wm + r) * SPW + col + 8 + cc] = v;
            v.x = c1[2] * scale; v.y = c1[3] * scale;
            *(float2*)&sP[(wm + r + 8) * SPW + col + 8 + cc] = v;
        }
    }
    __syncthreads();

    // ---- phase 2: softmax ----
    {
        const int q = t >> 2, part = t & 3;
        float* row = sP + q * SPW;
        const int s_lo = part * 128, s_hi = s_lo + 128;
        float mx = -1e30f;
        for (int s = s_lo; s < s_hi; ++s) mx = fmaxf(mx, row[s]);
        mx = fmaxf(mx, __shfl_xor_sync(0xffffffffu, mx, 1));
        mx = fmaxf(mx, __shfl_xor_sync(0xffffffffu, mx, 2));
        float sum = 0.f;
        for (int s = s_lo; s < s_hi; ++s) {
            float ev = __expf(row[s] - mx);
            row[s] = ev;
            sum += ev;
        }
        sum += __shfl_xor_sync(0xffffffffu, sum, 1);
        sum += __shfl_xor_sync(0xffffffffu, sum, 2);
        float inv = 1.0f / sum;
        for (int s = s_lo; s < s_hi; ++s) row[s] *= inv;
    }
    __syncthreads();

    // ---- phase 3: O = P @ V ----
    {
        const int wm = (warp & 3) * 16;
        const int wn = (warp >> 2) * 16;
        float o0[4] = {0,0,0,0}, o1[4] = {0,0,0,0};

#pragma unroll 4
        for (int kk = 0; kk < SK; kk += 16) {
            const float* p0 = &sP[(wm + r) * SPW + kk];
            const float* p1 = &sP[(wm + r + 8) * SPW + kk];
            float2 q00 = *(const float2*)&p0[cc];
            float2 q10 = *(const float2*)&p1[cc];
            float2 q01 = *(const float2*)&p0[cc + 8];
            float2 q11 = *(const float2*)&p1[cc + 8];
            uint32_t a[4];
            a[0] = pack_h2(q00.x, q00.y);
            a[1] = pack_h2(q10.x, q10.y);
            a[2] = pack_h2(q01.x, q01.y);
            a[3] = pack_h2(q11.x, q11.y);
            uint32_t bv[4];
            ldsm4(bv, smaddr(&sVt[(wn + lrow) * VLD + kk + lcol]));
            mma16816(o0, a, bv[0], bv[2]);
            mma16816(o1, a, bv[1], bv[3]);
        }

        long ob = ((long)b * LQ) * HE + h * EHD;
        *(__half2*)&Oh[ob + (long)(wm + r) * HE + wn + cc]
            = __floats2half2_rn(o0[0], o0[1]);
        *(__half2*)&Oh[ob + (long)(wm + r + 8) * HE + wn + cc]
            = __floats2half2_rn(o0[2], o0[3]);
        *(__half2*)&Oh[ob + (long)(wm + r) * HE + wn + 8 + cc]
            = __floats2half2_rn(o1[0], o1[1]);
        *(__half2*)&Oh[ob + (long)(wm + r + 8) * HE + wn + 8 + cc]
            = __floats2half2_rn(o1[2], o1[3]);
    }
}

// ------------------------- driver ------------------------------------------
extern "C" void kernel_launch(void* const* d_in, const int* in_sizes, int n_in,
                              void* d_out, int out_size)
{
    const float* enc  = (const float*)d_in[0];
    const float* pos  = (const float*)d_in[1];
    const float* wq   = (const float*)d_in[2];
    const float* wk   = (const float*)d_in[3];
    const float* wv   = (const float*)d_in[4];
    const float* wo   = (const float*)d_in[5];
    const float* ln1g = (const float*)d_in[6];
    const float* ln1b = (const float*)d_in[7];
    const float* ln2g = (const float*)d_in[8];
    const float* ln2b = (const float*)d_in[9];
    const float* w1   = (const float*)d_in[10];
    const float* w2   = (const float*)d_in[11];

    float *x, *tmp;
    cudaGetSymbolAddress((void**)&x,   g_x);
    cudaGetSymbolAddress((void**)&tmp, g_t);

    __half *xh,*eh,*Qh,*KVh,*Oh,*Hh;
    cudaGetSymbolAddress((void**)&xh,  g_xh);
    cudaGetSymbolAddress((void**)&eh,  g_eh);
    cudaGetSymbolAddress((void**)&Qh,  g_Qh);
    cudaGetSymbolAddress((void**)&KVh, g_KVh);
    cudaGetSymbolAddress((void**)&Oh,  g_Oh);
    cudaGetSymbolAddress((void**)&Hh,  g_Hh);

    __half *wqp,*wkvp,*wop,*w1p,*w2p;
    cudaGetSymbolAddress((void**)&wqp,  g_wq);
    cudaGetSymbolAddress((void**)&wkvp, g_wkv);
    cudaGetSymbolAddress((void**)&wop,  g_wo);
    cudaGetSymbolAddress((void**)&w1p,  g_w1);
    cudaGetSymbolAddress((void**)&w2p,  g_w2);

    cudaFuncSetAttribute(attn_kernel, cudaFuncAttributeMaxDynamicSharedMemorySize,
                         ATTN_SMEM);
    cudaFuncSetAttribute(mma_gemm, cudaFuncAttributeMaxDynamicSharedMemorySize,
                         GEMM_SMEM);

    {
        int n = NB * HE * DIM;
        repack_qkv<<<(n + 255) / 256, 256>>>(wq, wqp);
        repack_wo <<<(n + 255) / 256, 256>>>(wo, wop);
        int nkv = NB * NKV * DIM;
        repack_kv<<<(nkv + 255) / 256, 256>>>(wk, wv, wkvp);
        int nf = NB * DIM * HID;
        repack_ffn<<<(nf + 255) / 256, 256>>>(w1, w1p, DIM, HID);
        repack_ffn<<<(nf + 255) / 256, 256>>>(w2, w2p, HID, DIM);
    }
    init_x_kernel<<<(MQ * DIM + 255) / 256, 256>>>(pos, x, xh);
    cvt4_kernel<<<(MKV * DIM / 4 + 255) / 256, 256>>>(enc, eh, MKV * DIM / 4);

    dim3 gQ  (MQ  / 128, HE  / 128);  // 32 x 3
    dim3 gKV (MKV / 128, NKV / 128);  // 256 x 6
    dim3 gO  (MQ  / 128, DIM / 128);  // 32 x 6
    dim3 gF1 (MQ  / 128, HID / 128);  // 32 x 24
    dim3 gF2 (MQ  / 128, DIM / 128);  // 32 x 6

    for (int i = 0; i < NB; ++i) {
        const long woff   = (long)i * DIM * HE;
        const long wkvoff = (long)i * DIM * NKV;
        const long w1off  = (long)i * DIM * HID;
        const long w2off  = (long)i * HID * DIM;

        mma_gemm<<<gQ,  256, GEMM_SMEM>>>(xh, wqp + woff,
                                          nullptr, nullptr, Qh, MQ,  HE, DIM, 3);
        mma_gemm<<<gKV, 256, GEMM_SMEM>>>(eh, wkvp + wkvoff,
                                          nullptr, nullptr, KVh, MKV, NKV, DIM, 3);

        attn_kernel<<<BATCH * HEADS, 256, ATTN_SMEM>>>(Qh, KVh, Oh);

        mma_gemm<<<gO, 256, GEMM_SMEM>>>(Oh, wop + woff,
                                         x, tmp, nullptr, MQ, DIM, HE, 2);
        ln_kernel<<<MQ, 256>>>(tmp, ln1g + i * DIM, ln1b + i * DIM, x, xh);

        mma_gemm<<<gF1, 256, GEMM_SMEM>>>(xh, w1p + w1off,
                                          nullptr, nullptr, Hh, MQ, HID, DIM, 1);
        mma_gemm<<<gF2, 256, GEMM_SMEM>>>(Hh, w2p + w2off,
                                          x, tmp, nullptr, MQ, DIM, HID, 2);
        ln_kernel<<<MQ, 256>>>(tmp, ln2g + i * DIM, ln2b + i * DIM,
                               (i == NB - 1) ? (float*)d_out : x, xh);
    }
}